// round 1
// baseline (speedup 1.0000x reference)
#include <cuda_runtime.h>
#include <math.h>

// ---------------- problem constants ----------------
#define B_ 2
#define T_ 512
#define D_ 256
#define NH 4
#define NS 4096          // sparse dim N = D*mult/nh
#define V_ 256
#define NLAYER 6
#define LN_EPSF 1e-5f
#define TWO_PI 6.283185307179586f

#define LOGITS_OFF 0
#define EMB_OFF (B_*T_*V_)            // 262144
#define TRACE_OFF (EMB_OFF + B_*D_)   // 262656

// ---------------- scratch (static device globals; no allocation) ----------------
__device__ float g_x[B_*T_*D_];                       // current x (B,T,D)
__device__ float g_xs[(size_t)B_*NH*T_*NS];           // x_sparse -> xy_sparse
__device__ float g_qr[(size_t)B_*NH*T_*NS];           // rope(x_sparse)
__device__ float g_sc[(size_t)B_*NH*T_*T_];           // scores
__device__ float g_ykv[B_*NH*T_*D_];                  // ykv
__device__ float g_part[NH*B_*T_*D_];                 // per-h decoder partials
__device__ float g_cs[(size_t)T_*NS];                 // rope cos table
__device__ float g_sn[(size_t)T_*NS];                 // rope sin table
__device__ int   g_ids[B_*T_];

// ---------------- helpers ----------------
__device__ __forceinline__ float block_ln(float v, float* red) {
    const int tid = threadIdx.x;
    red[tid] = v; __syncthreads();
#pragma unroll
    for (int s = 128; s >= 1; s >>= 1) { if (tid < s) red[tid] += red[tid + s]; __syncthreads(); }
    const float mu = red[0] * (1.0f / D_);
    __syncthreads();
    const float d = v - mu;
    red[tid] = d * d; __syncthreads();
#pragma unroll
    for (int s = 128; s >= 1; s >>= 1) { if (tid < s) red[tid] += red[tid + s]; __syncthreads(); }
    const float var = red[0] * (1.0f / D_);
    __syncthreads();
    return d * rsqrtf(var + LN_EPSF);
}

// ---------------- tiny prep kernels ----------------
// input_ids declared int64 in the reference, but jax x64-canonicalization may
// deliver int32. Detect: if all odd 32-bit words of the first 1024 ints are 0,
// it's little-endian int64 (values < 256 -> high words are 0). With int32 data
// those words are 512 random indices in [0,256): P(all zero) ~ 256^-512.
__global__ void k_decode(const int* __restrict__ p) {
    __shared__ int nz;
    if (threadIdx.x == 0) nz = 0;
    __syncthreads();
    for (int i = threadIdx.x; i < (B_*T_) / 2; i += blockDim.x)
        if (p[2*i + 1] != 0) atomicOr(&nz, 1);
    __syncthreads();
    const bool is64 = (nz == 0);
    const long long* pl = (const long long*)p;
    for (int i = threadIdx.x; i < B_*T_; i += blockDim.x)
        g_ids[i] = is64 ? (int)pl[i] : p[i];
}

__global__ void k_embed(const float* __restrict__ emb) {
    __shared__ float red[256];
    const int row = blockIdx.x;           // b*T+t
    const int id = g_ids[row];
    const float v = emb[(size_t)id * D_ + threadIdx.x];
    g_x[(size_t)row * D_ + threadIdx.x] = block_ln(v, red);
}

__global__ void k_rope_tab() {
    const int idx = blockIdx.x * blockDim.x + threadIdx.x;  // t*NS + n
    const int t = idx / NS, n = idx % NS;
    const float qidx = (float)((n >> 1) << 1);
    // THETA = 2^16  ->  theta^(-qidx/N) = 2^(-16*qidx/N)
    const float freq = exp2f(-16.0f * qidx / (float)NS) * (1.0f / TWO_PI);
    float ph = (float)t * freq;
    ph -= floorf(ph);
    const float a = ph * TWO_PI;
    g_cs[idx] = cosf(a);
    g_sn[idx] = sinf(a);
}

__global__ void k_zero_sc() {
    const size_t i = (size_t)blockIdx.x * blockDim.x + threadIdx.x;
    g_sc[i] = 0.f;
}

// ---------------- the GEMM workhorse ----------------
// OP=1: x_sparse = relu(x @ encoder[h]); qr = rope(x_sparse).  z = h. M=B*T, N=NS, K=D
// OP=2: scores = qr @ qr^T (causal strict lower).              z = b*nh+h. M=N=T, K=NS
// OP=3: ykv = scores @ x[b].                                   z = b*nh+h. M=T, N=D, K=T
// OP=4: xy = relu(ykv @ encoder_v[h]) * x_sparse (in place).   z = b*nh+h. M=T, N=NS, K=D
// OP=5: part[h] = xy[:,h] @ dec[h].                            z = h. M=B*T, N=D, K=NS
// OP=6: logits = x @ lm_head.                                  M=B*T, N=V, K=D
template<int OP, int BM, int BN, int BK, int TM, int TN, bool TB>
__global__ void __launch_bounds__(256) k_gemm(const float* __restrict__ P1,
                                              float* __restrict__ Pout) {
    const int z  = blockIdx.z;
    const int tid = threadIdx.x;
    const int m0 = blockIdx.y * BM;
    const int n0 = blockIdx.x * BN;

    if constexpr (OP == 2) {
        // entire tile strictly above/on diagonal -> stays zero (pre-zeroed once)
        if (n0 >= m0 + BM) return;
    }

    int K = 0, lda = 0, ldb = 0;
    const float* Ap = nullptr; const float* Bp = nullptr;
    if constexpr (OP == 1) { K = D_; Ap = g_x;                           lda = D_; Bp = P1 + (size_t)z*D_*NS;        ldb = NS; }
    if constexpr (OP == 2) { K = NS; Ap = g_qr + (size_t)z*T_*NS;        lda = NS; Bp = Ap;                          ldb = NS; }
    if constexpr (OP == 3) { K = T_; Ap = g_sc + (size_t)z*T_*T_;        lda = T_; Bp = g_x + (size_t)(z/NH)*T_*D_;  ldb = D_; }
    if constexpr (OP == 4) { K = D_; Ap = g_ykv + (size_t)z*T_*D_;       lda = D_; Bp = P1 + (size_t)(z%NH)*D_*NS;   ldb = NS; }
    if constexpr (OP == 5) { K = NS;                                               Bp = P1 + (size_t)z*NS*D_;        ldb = D_; }
    if constexpr (OP == 6) { K = D_; Ap = g_x;                           lda = D_; Bp = P1;                          ldb = V_; }

    __shared__ __align__(16) float As[BK][BM];
    __shared__ __align__(16) float Bs[BK][BN];

    float acc[TM][TN];
#pragma unroll
    for (int i = 0; i < TM; i++)
#pragma unroll
        for (int j = 0; j < TN; j++) acc[i][j] = 0.f;

    const int ty = tid / (BN / TN);
    const int tx = tid % (BN / TN);

    for (int k0 = 0; k0 < K; k0 += BK) {
        // --- load A tile (K-contiguous in gmem), store transposed As[k][m] ---
        {
            constexpr int K4 = BK / 4;
            constexpr int RPI = 256 / K4;
#pragma unroll
            for (int r0 = 0; r0 < BM; r0 += RPI) {
                const int r = r0 + tid / K4;
                const int c = (tid % K4) * 4;
                float4 v;
                if constexpr (OP == 5) {
                    const int m = m0 + r;
                    const size_t off = ((size_t)((m / T_) * NH + z) * T_ + (m % T_)) * NS + k0 + c;
                    v = *(const float4*)&g_xs[off];
                } else {
                    v = *(const float4*)&Ap[(size_t)(m0 + r) * lda + k0 + c];
                }
                As[c + 0][r] = v.x; As[c + 1][r] = v.y; As[c + 2][r] = v.z; As[c + 3][r] = v.w;
            }
        }
        // --- load B tile ---
        if constexpr (TB) {  // B rows are the N dim, K-contiguous -> transpose
            constexpr int K4 = BK / 4;
            constexpr int RPI = 256 / K4;
#pragma unroll
            for (int r0 = 0; r0 < BN; r0 += RPI) {
                const int r = r0 + tid / K4;
                const int c = (tid % K4) * 4;
                const float4 v = *(const float4*)&Bp[(size_t)(n0 + r) * ldb + k0 + c];
                Bs[c + 0][r] = v.x; Bs[c + 1][r] = v.y; Bs[c + 2][r] = v.z; Bs[c + 3][r] = v.w;
            }
        } else {             // B row-major K x N, N-contiguous
            constexpr int N4 = BN / 4;
            constexpr int RPI = 256 / N4;
#pragma unroll
            for (int r0 = 0; r0 < BK; r0 += RPI) {
                const int r = r0 + tid / N4;
                const int c = (tid % N4) * 4;
                *(float4*)&Bs[r][c] = *(const float4*)&Bp[(size_t)(k0 + r) * ldb + n0 + c];
            }
        }
        __syncthreads();
        // --- compute ---
#pragma unroll
        for (int kk = 0; kk < BK; kk++) {
            float ra[TM], rb[TN];
#pragma unroll
            for (int i = 0; i < TM; i += 4) *(float4*)&ra[i] = *(const float4*)&As[kk][ty * TM + i];
#pragma unroll
            for (int j = 0; j < TN; j += 4) *(float4*)&rb[j] = *(const float4*)&Bs[kk][tx * TN + j];
#pragma unroll
            for (int i = 0; i < TM; i++)
#pragma unroll
                for (int j = 0; j < TN; j++) acc[i][j] = fmaf(ra[i], rb[j], acc[i][j]);
        }
        __syncthreads();
    }

    // --- epilogues ---
    if constexpr (OP == 1) {
#pragma unroll
        for (int i = 0; i < TM; i++) {
            const int m = m0 + ty * TM + i;
            const int b = m / T_, t = m % T_;
            const size_t ob = ((size_t)(b * NH + z) * T_ + t) * NS;
            const size_t ct = (size_t)t * NS;
#pragma unroll
            for (int j = 0; j < TN; j += 2) {
                const int n = n0 + tx * TN + j;
                const float v0 = fmaxf(acc[i][j], 0.f);
                const float v1 = fmaxf(acc[i][j + 1], 0.f);
                g_xs[ob + n]     = v0;
                g_xs[ob + n + 1] = v1;
                const float c = g_cs[ct + n];
                const float s = g_sn[ct + n];
                g_qr[ob + n]     = v0 * c - v1 * s;
                g_qr[ob + n + 1] = v1 * c + v0 * s;
            }
        }
    }
    if constexpr (OP == 2) {
#pragma unroll
        for (int i = 0; i < TM; i++) {
            const int t = m0 + ty * TM + i;
            const size_t ob = (size_t)z * T_ * T_ + (size_t)t * T_;
#pragma unroll
            for (int j = 0; j < TN; j++) {
                const int s = n0 + tx * TN + j;
                g_sc[ob + s] = (s < t) ? acc[i][j] : 0.f;
            }
        }
    }
    if constexpr (OP == 3) {
#pragma unroll
        for (int i = 0; i < TM; i++) {
            const int m = m0 + ty * TM + i;
#pragma unroll
            for (int j = 0; j < TN; j++) {
                const int n = n0 + tx * TN + j;
                g_ykv[(size_t)z * T_ * D_ + (size_t)m * D_ + n] = acc[i][j];
            }
        }
    }
    if constexpr (OP == 4) {
#pragma unroll
        for (int i = 0; i < TM; i++) {
            const int m = m0 + ty * TM + i;
            const size_t ob = ((size_t)z * T_ + m) * NS;
#pragma unroll
            for (int j = 0; j < TN; j++) {
                const int n = n0 + tx * TN + j;
                g_xs[ob + n] = fmaxf(acc[i][j], 0.f) * g_xs[ob + n];
            }
        }
    }
    if constexpr (OP == 5) {
#pragma unroll
        for (int i = 0; i < TM; i++) {
            const int m = m0 + ty * TM + i;
#pragma unroll
            for (int j = 0; j < TN; j++) {
                const int n = n0 + tx * TN + j;
                g_part[((size_t)z * (B_*T_) + m) * D_ + n] = acc[i][j];
            }
        }
    }
    if constexpr (OP == 6) {
#pragma unroll
        for (int i = 0; i < TM; i++) {
            const int m = m0 + ty * TM + i;
#pragma unroll
            for (int j = 0; j < TN; j++) {
                const int n = n0 + tx * TN + j;
                Pout[(size_t)m * V_ + n] = acc[i][j];
            }
        }
    }
}

// ---------------- LN / reduction kernels ----------------
__global__ void k_ln_ykv() {
    __shared__ float red[256];
    const size_t o = (size_t)blockIdx.x * D_ + threadIdx.x;
    const float v = g_ykv[o];
    g_ykv[o] = block_ln(v, red);
}

__global__ void k_layer_end() {
    __shared__ float red[256];
    const int row = blockIdx.x;  // b*T+t
    float s = 0.f;
#pragma unroll
    for (int h = 0; h < NH; h++)
        s += g_part[((size_t)h * (B_*T_) + row) * D_ + threadIdx.x];
    const float yn = block_ln(s, red);
    const size_t o = (size_t)row * D_ + threadIdx.x;
    const float xv = g_x[o] + yn;
    g_x[o] = block_ln(xv, red);
}

__global__ void k_emb_mean(float* __restrict__ out) {
    const int idx = blockIdx.x * blockDim.x + threadIdx.x;  // < B_*D_
    const int b = idx / D_, d = idx % D_;
    float s = 0.f;
    for (int t = 0; t < T_; t++) s += g_x[((size_t)(b * T_ + t)) * D_ + d];
    out[EMB_OFF + idx] = s * (1.0f / T_);
}

__global__ void k_trace_mean(float* __restrict__ out) {
    const int idx = blockIdx.x * blockDim.x + threadIdx.x;  // < B_*NH*NS
    const int zz = idx / NS, n = idx % NS;
    float s = 0.f;
    for (int t = 0; t < T_; t++) s += g_xs[((size_t)(zz * T_ + t)) * NS + n];
    out[TRACE_OFF + idx] = s * (1.0f / T_);
}

// ---------------- driver ----------------
extern "C" void kernel_launch(void* const* d_in, const int* in_sizes, int n_in,
                              void* d_out, int out_size) {
    const int*   ids  = (const int*)  d_in[0];
    const float* emb  = (const float*)d_in[1];
    const float* enc  = (const float*)d_in[2];
    const float* encv = (const float*)d_in[3];
    const float* dec  = (const float*)d_in[4];
    const float* lmh  = (const float*)d_in[5];
    float* out = (float*)d_out;
    (void)in_sizes; (void)n_in; (void)out_size;

    k_decode<<<1, 256>>>(ids);
    k_rope_tab<<<(T_ * NS) / 256, 256>>>();
    k_zero_sc<<<(B_*NH*T_*T_) / 256, 256>>>();
    k_embed<<<B_*T_, 256>>>(emb);

    for (int l = 0; l < NLAYER; l++) {
        // x_sparse + rope
        k_gemm<1, 128, 128, 16, 8, 8, false><<<dim3(NS/128, (B_*T_)/128, NH), 256>>>(enc, nullptr);
        // scores (causal)
        k_gemm<2, 128,  64, 16, 8, 4, true ><<<dim3(T_/64,  T_/128, B_*NH), 256>>>(nullptr, nullptr);
        // ykv
        k_gemm<3,  64,  64, 16, 4, 4, false><<<dim3(D_/64,  T_/64,  B_*NH), 256>>>(nullptr, nullptr);
        k_ln_ykv<<<B_*NH*T_, 256>>>();
        // y_sparse * x_sparse (in place)
        k_gemm<4, 128, 128, 16, 8, 8, false><<<dim3(NS/128, T_/128, B_*NH), 256>>>(encv, nullptr);
        // decoder partials per h
        k_gemm<5,  64,  64, 16, 4, 4, false><<<dim3(D_/64, (B_*T_)/64, NH), 256>>>(dec, nullptr);
        // sum over h + ln + residual + ln
        k_layer_end<<<B_*T_, 256>>>();
    }

    // logits
    k_gemm<6, 64, 64, 16, 4, 4, false><<<dim3(V_/64, (B_*T_)/64, 1), 256>>>(lmh, out);
    // embedding = mean over T
    k_emb_mean<<<(B_*D_) / 256, 256>>>(out);
    // neuron_trace = mean over T of last layer's xy_sparse
    k_trace_mean<<<(B_*NH*NS) / 256, 256>>>(out);
}

// round 2
// speedup vs baseline: 1.1264x; 1.1264x over previous
#include <cuda_runtime.h>
#include <math.h>

// ---------------- problem constants ----------------
#define B_ 2
#define T_ 512
#define D_ 256
#define NH 4
#define NS 4096          // sparse dim N = D*mult/nh
#define V_ 256
#define NLAYER 6
#define LN_EPSF 1e-5f
#define TWO_PI 6.283185307179586f

#define LOGITS_OFF 0
#define EMB_OFF (B_*T_*V_)            // 262144
#define TRACE_OFF (EMB_OFF + B_*D_)   // 262656

// ---------------- scratch (static device globals; no allocation) ----------------
__device__ float g_x[B_*T_*D_];                       // current x (B,T,D)
__device__ float g_xs[(size_t)B_*NH*T_*NS];           // x_sparse -> xy_sparse
__device__ float g_qr[(size_t)B_*NH*T_*NS];           // rope(x_sparse)
__device__ float g_sc[(size_t)B_*NH*T_*T_];           // scores
__device__ float g_ykv[B_*NH*T_*D_];                  // ykv
__device__ float g_part[NH*B_*T_*D_];                 // per-h decoder partials
__device__ float g_cs[(size_t)T_*NS];                 // rope cos table
__device__ float g_sn[(size_t)T_*NS];                 // rope sin table
__device__ int   g_ids[B_*T_];

// ---------------- helpers ----------------
__device__ __forceinline__ float block_ln(float v, float* red) {
    const int tid = threadIdx.x;
    red[tid] = v; __syncthreads();
#pragma unroll
    for (int s = 128; s >= 1; s >>= 1) { if (tid < s) red[tid] += red[tid + s]; __syncthreads(); }
    const float mu = red[0] * (1.0f / D_);
    __syncthreads();
    const float d = v - mu;
    red[tid] = d * d; __syncthreads();
#pragma unroll
    for (int s = 128; s >= 1; s >>= 1) { if (tid < s) red[tid] += red[tid + s]; __syncthreads(); }
    const float var = red[0] * (1.0f / D_);
    __syncthreads();
    return d * rsqrtf(var + LN_EPSF);
}

// ---------------- tiny prep kernels ----------------
__global__ void k_decode(const int* __restrict__ p) {
    __shared__ int nz;
    if (threadIdx.x == 0) nz = 0;
    __syncthreads();
    for (int i = threadIdx.x; i < (B_*T_) / 2; i += blockDim.x)
        if (p[2*i + 1] != 0) atomicOr(&nz, 1);
    __syncthreads();
    const bool is64 = (nz == 0);
    const long long* pl = (const long long*)p;
    for (int i = threadIdx.x; i < B_*T_; i += blockDim.x)
        g_ids[i] = is64 ? (int)pl[i] : p[i];
}

__global__ void k_embed(const float* __restrict__ emb) {
    __shared__ float red[256];
    const int row = blockIdx.x;           // b*T+t
    const int id = g_ids[row];
    const float v = emb[(size_t)id * D_ + threadIdx.x];
    g_x[(size_t)row * D_ + threadIdx.x] = block_ln(v, red);
}

__global__ void k_rope_tab() {
    const int idx = blockIdx.x * blockDim.x + threadIdx.x;  // t*NS + n
    const int t = idx / NS, n = idx % NS;
    const float qidx = (float)((n >> 1) << 1);
    const float freq = exp2f(-16.0f * qidx / (float)NS) * (1.0f / TWO_PI);
    float ph = (float)t * freq;
    ph -= floorf(ph);
    const float a = ph * TWO_PI;
    g_cs[idx] = cosf(a);
    g_sn[idx] = sinf(a);
}

__global__ void k_zero_sc() {
    const size_t i = (size_t)blockIdx.x * blockDim.x + threadIdx.x;
    g_sc[i] = 0.f;
}

// ---------------- the GEMM workhorse (double-buffered, reg-staged) ----------------
// OP=1: x_sparse = relu(x @ encoder[h]); qr = rope(x_sparse).  z = h. M=B*T, N=NS, K=D
// OP=2: scores = qr @ qr^T (causal strict lower).              z = b*nh+h. M=N=T, K=NS
// OP=3: ykv = scores @ x[b].                                   z = b*nh+h. M=T, N=D, K=T
// OP=4: xy = relu(ykv @ encoder_v[h]) * x_sparse (in place).   z = b*nh+h. M=T, N=NS, K=D
// OP=5: part[h] = xy[:,h] @ dec[h].                            z = h. M=B*T, N=D, K=NS
// OP=6: logits = x @ lm_head.                                  M=B*T, N=V, K=D
template<int OP, int BM, int BN, int BK, int TM, int TN, bool TB>
__global__ void __launch_bounds__(256) k_gemm(const float* __restrict__ P1,
                                              float* __restrict__ Pout) {
    const int z  = blockIdx.z;
    const int tid = threadIdx.x;
    const int m0 = blockIdx.y * BM;
    const int n0 = blockIdx.x * BN;

    if constexpr (OP == 2) {
        if (n0 >= m0 + BM) return;   // fully-masked tile (g_sc pre-zeroed once)
    }

    int K = 0, lda = 0, ldb = 0;
    const float* Ap = nullptr; const float* Bp = nullptr;
    if constexpr (OP == 1) { K = D_; Ap = g_x;                           lda = D_; Bp = P1 + (size_t)z*D_*NS;        ldb = NS; }
    if constexpr (OP == 2) { K = NS; Ap = g_qr + (size_t)z*T_*NS;        lda = NS; Bp = Ap;                          ldb = NS; }
    if constexpr (OP == 3) { K = T_; Ap = g_sc + (size_t)z*T_*T_;        lda = T_; Bp = g_x + (size_t)(z/NH)*T_*D_;  ldb = D_; }
    if constexpr (OP == 4) { K = D_; Ap = g_ykv + (size_t)z*T_*D_;       lda = D_; Bp = P1 + (size_t)(z%NH)*D_*NS;   ldb = NS; }
    if constexpr (OP == 5) { K = NS;                                               Bp = P1 + (size_t)z*NS*D_;        ldb = D_; }
    if constexpr (OP == 6) { K = D_; Ap = g_x;                           lda = D_; Bp = P1;                          ldb = V_; }

    // staging geometry
    constexpr int K4   = BK / 4;        // float4 per A/B(T) row
    constexpr int RPI  = 256 / K4;      // rows loaded per pass
    constexpr int NA   = BM / RPI;      // float4 per thread, A tile
    constexpr int NBt  = (BN >= RPI) ? BN / RPI : 1;  // float4 per thread, B tile (TB)
    constexpr int N4   = BN / 4;
    constexpr int RPIB = 256 / N4;
    constexpr int NBn  = (BK >= RPIB) ? BK / RPIB : 1; // float4 per thread, B tile (!TB)

    __shared__ __align__(16) float As[2][BK][BM];
    __shared__ __align__(16) float Bs[2][BK][BN];

    float acc[TM][TN];
#pragma unroll
    for (int i = 0; i < TM; i++)
#pragma unroll
        for (int j = 0; j < TN; j++) acc[i][j] = 0.f;

    const int ty = tid / (BN / TN);
    const int tx = tid % (BN / TN);

    float4 va[NA];
    float4 vb[TB ? NBt : NBn];

    // ---- LDG of tile k0 into regs ----
    auto ldg_tiles = [&](int k0) {
#pragma unroll
        for (int u = 0; u < NA; u++) {
            const int r = u * RPI + tid / K4;
            const int c = (tid % K4) * 4;
            if constexpr (OP == 5) {
                const int m = m0 + r;
                const size_t off = ((size_t)((m / T_) * NH + z) * T_ + (m % T_)) * NS + k0 + c;
                va[u] = *(const float4*)&g_xs[off];
            } else {
                va[u] = *(const float4*)&Ap[(size_t)(m0 + r) * lda + k0 + c];
            }
        }
        if constexpr (TB) {
#pragma unroll
            for (int u = 0; u < NBt; u++) {
                const int r = u * RPI + tid / K4;
                const int c = (tid % K4) * 4;
                vb[u] = *(const float4*)&Bp[(size_t)(n0 + r) * ldb + k0 + c];
            }
        } else {
#pragma unroll
            for (int u = 0; u < NBn; u++) {
                const int r = u * RPIB + tid / N4;
                const int c = (tid % N4) * 4;
                vb[u] = *(const float4*)&Bp[(size_t)(k0 + r) * ldb + n0 + c];
            }
        }
    };
    // ---- STS of staged regs into buffer s ----
    auto sts_tiles = [&](int s) {
#pragma unroll
        for (int u = 0; u < NA; u++) {
            const int r = u * RPI + tid / K4;
            const int c = (tid % K4) * 4;
            As[s][c + 0][r] = va[u].x; As[s][c + 1][r] = va[u].y;
            As[s][c + 2][r] = va[u].z; As[s][c + 3][r] = va[u].w;
        }
        if constexpr (TB) {
#pragma unroll
            for (int u = 0; u < NBt; u++) {
                const int r = u * RPI + tid / K4;
                const int c = (tid % K4) * 4;
                Bs[s][c + 0][r] = vb[u].x; Bs[s][c + 1][r] = vb[u].y;
                Bs[s][c + 2][r] = vb[u].z; Bs[s][c + 3][r] = vb[u].w;
            }
        } else {
#pragma unroll
            for (int u = 0; u < NBn; u++) {
                const int r = u * RPIB + tid / N4;
                const int c = (tid % N4) * 4;
                *(float4*)&Bs[s][r][c] = vb[u];
            }
        }
    };

    const int nt = K / BK;
    ldg_tiles(0);
    for (int t = 0; t < nt; t++) {
        const int s = t & 1;
        sts_tiles(s);
        __syncthreads();
        if (t + 1 < nt) ldg_tiles((t + 1) * BK);
        // compute from buffer s
#pragma unroll
        for (int kk = 0; kk < BK; kk++) {
            float ra[TM], rb[TN];
#pragma unroll
            for (int i = 0; i < TM; i += 4) *(float4*)&ra[i] = *(const float4*)&As[s][kk][ty * TM + i];
#pragma unroll
            for (int j = 0; j < TN; j += 4) *(float4*)&rb[j] = *(const float4*)&Bs[s][kk][tx * TN + j];
#pragma unroll
            for (int i = 0; i < TM; i++)
#pragma unroll
                for (int j = 0; j < TN; j++) acc[i][j] = fmaf(ra[i], rb[j], acc[i][j]);
        }
        // NOTE: single sync per iteration is sufficient: tile t+2's STS (same
        // buffer as t) can only start after every thread passed the sync at the
        // top of iteration t+1, which is after every thread finished compute(t).
    }

    // --- epilogues ---
    if constexpr (OP == 1) {
#pragma unroll
        for (int i = 0; i < TM; i++) {
            const int m = m0 + ty * TM + i;
            const int b = m / T_, t = m % T_;
            const size_t ob = ((size_t)(b * NH + z) * T_ + t) * NS;
            const size_t ct = (size_t)t * NS;
#pragma unroll
            for (int j = 0; j < TN; j += 2) {
                const int n = n0 + tx * TN + j;
                const float v0 = fmaxf(acc[i][j], 0.f);
                const float v1 = fmaxf(acc[i][j + 1], 0.f);
                g_xs[ob + n]     = v0;
                g_xs[ob + n + 1] = v1;
                const float c = g_cs[ct + n];
                const float sn = g_sn[ct + n];
                g_qr[ob + n]     = v0 * c - v1 * sn;
                g_qr[ob + n + 1] = v1 * c + v0 * sn;
            }
        }
    }
    if constexpr (OP == 2) {
#pragma unroll
        for (int i = 0; i < TM; i++) {
            const int t = m0 + ty * TM + i;
            const size_t ob = (size_t)z * T_ * T_ + (size_t)t * T_;
#pragma unroll
            for (int j = 0; j < TN; j++) {
                const int s2 = n0 + tx * TN + j;
                g_sc[ob + s2] = (s2 < t) ? acc[i][j] : 0.f;
            }
        }
    }
    if constexpr (OP == 3) {
#pragma unroll
        for (int i = 0; i < TM; i++) {
            const int m = m0 + ty * TM + i;
#pragma unroll
            for (int j = 0; j < TN; j++) {
                const int n = n0 + tx * TN + j;
                g_ykv[(size_t)z * T_ * D_ + (size_t)m * D_ + n] = acc[i][j];
            }
        }
    }
    if constexpr (OP == 4) {
#pragma unroll
        for (int i = 0; i < TM; i++) {
            const int m = m0 + ty * TM + i;
            const size_t ob = ((size_t)z * T_ + m) * NS;
#pragma unroll
            for (int j = 0; j < TN; j++) {
                const int n = n0 + tx * TN + j;
                g_xs[ob + n] = fmaxf(acc[i][j], 0.f) * g_xs[ob + n];
            }
        }
    }
    if constexpr (OP == 5) {
#pragma unroll
        for (int i = 0; i < TM; i++) {
            const int m = m0 + ty * TM + i;
#pragma unroll
            for (int j = 0; j < TN; j++) {
                const int n = n0 + tx * TN + j;
                g_part[((size_t)z * (B_*T_) + m) * D_ + n] = acc[i][j];
            }
        }
    }
    if constexpr (OP == 6) {
#pragma unroll
        for (int i = 0; i < TM; i++) {
            const int m = m0 + ty * TM + i;
#pragma unroll
            for (int j = 0; j < TN; j++) {
                const int n = n0 + tx * TN + j;
                Pout[(size_t)m * V_ + n] = acc[i][j];
            }
        }
    }
}

// ---------------- LN / reduction kernels ----------------
__global__ void k_ln_ykv() {
    __shared__ float red[256];
    const size_t o = (size_t)blockIdx.x * D_ + threadIdx.x;
    const float v = g_ykv[o];
    g_ykv[o] = block_ln(v, red);
}

__global__ void k_layer_end() {
    __shared__ float red[256];
    const int row = blockIdx.x;  // b*T+t
    float s = 0.f;
#pragma unroll
    for (int h = 0; h < NH; h++)
        s += g_part[((size_t)h * (B_*T_) + row) * D_ + threadIdx.x];
    const float yn = block_ln(s, red);
    const size_t o = (size_t)row * D_ + threadIdx.x;
    const float xv = g_x[o] + yn;
    g_x[o] = block_ln(xv, red);
}

__global__ void k_emb_mean(float* __restrict__ out) {
    const int idx = blockIdx.x * blockDim.x + threadIdx.x;  // < B_*D_
    const int b = idx / D_, d = idx % D_;
    float s = 0.f;
    for (int t = 0; t < T_; t++) s += g_x[((size_t)(b * T_ + t)) * D_ + d];
    out[EMB_OFF + idx] = s * (1.0f / T_);
}

__global__ void k_trace_mean(float* __restrict__ out) {
    const int idx = blockIdx.x * blockDim.x + threadIdx.x;  // < B_*NH*NS
    const int zz = idx / NS, n = idx % NS;
    float s = 0.f;
    for (int t = 0; t < T_; t++) s += g_xs[((size_t)(zz * T_ + t)) * NS + n];
    out[TRACE_OFF + idx] = s * (1.0f / T_);
}

// ---------------- driver ----------------
extern "C" void kernel_launch(void* const* d_in, const int* in_sizes, int n_in,
                              void* d_out, int out_size) {
    const int*   ids  = (const int*)  d_in[0];
    const float* emb  = (const float*)d_in[1];
    const float* enc  = (const float*)d_in[2];
    const float* encv = (const float*)d_in[3];
    const float* dec  = (const float*)d_in[4];
    const float* lmh  = (const float*)d_in[5];
    float* out = (float*)d_out;
    (void)in_sizes; (void)n_in; (void)out_size;

    k_decode<<<1, 256>>>(ids);
    k_rope_tab<<<(T_ * NS) / 256, 256>>>();
    k_zero_sc<<<(B_*NH*T_*T_) / 256, 256>>>();
    k_embed<<<B_*T_, 256>>>(emb);

    for (int l = 0; l < NLAYER; l++) {
        // x_sparse + rope
        k_gemm<1, 128, 128, 16, 8, 8, false><<<dim3(NS/128, (B_*T_)/128, NH), 256>>>(enc, nullptr);
        // scores (causal)
        k_gemm<2, 128,  64, 16, 8, 4, true ><<<dim3(T_/64,  T_/128, B_*NH), 256>>>(nullptr, nullptr);
        // ykv
        k_gemm<3,  64,  64, 16, 4, 4, false><<<dim3(D_/64,  T_/64,  B_*NH), 256>>>(nullptr, nullptr);
        k_ln_ykv<<<B_*NH*T_, 256>>>();
        // y_sparse * x_sparse (in place)
        k_gemm<4, 128, 128, 16, 8, 8, false><<<dim3(NS/128, T_/128, B_*NH), 256>>>(encv, nullptr);
        // decoder partials per h
        k_gemm<5,  64,  64, 16, 4, 4, false><<<dim3(D_/64, (B_*T_)/64, NH), 256>>>(dec, nullptr);
        // sum over h + ln + residual + ln
        k_layer_end<<<B_*T_, 256>>>();
    }

    // logits
    k_gemm<6, 64, 64, 16, 4, 4, false><<<dim3(V_/64, (B_*T_)/64, 1), 256>>>(lmh, out);
    // embedding = mean over T
    k_emb_mean<<<(B_*D_) / 256, 256>>>(out);
    // neuron_trace = mean over T of last layer's xy_sparse
    k_trace_mean<<<(B_*NH*NS) / 256, 256>>>(out);
}